// round 12
// baseline (speedup 1.0000x reference)
#include <cuda_runtime.h>
#include <cstdint>

#define FEAT_DIM    1024
#define BLK_THREADS 256
#define WARPS_BLK   8
#define GRID_BLKS   1216            // 152 SMs x 8 blocks -> one wave, 64 warps/SM
#define MAX_BLOCKS  2048
#define NBUF        3               // per-warp cp.async ring depth
#define CHUNKS      8               // 8 x 512B chunks per 4KB row

// Static scratch (allocation-free per harness rules)
__device__ float        g_partials[MAX_BLOCKS];
__device__ unsigned int g_done;     // self-resetting last-block counter

__device__ __forceinline__ void cp_async16(uint32_t dst, const void* src) {
    asm volatile("cp.async.cg.shared.global [%0], [%1], 16;"
                 :: "r"(dst), "l"(src) : "memory");
}
__device__ __forceinline__ void cp_commit() {
    asm volatile("cp.async.commit_group;" ::: "memory");
}
template <int N>
__device__ __forceinline__ void cp_wait() {
    asm volatile("cp.async.wait_group %0;" :: "n"(N) : "memory");
}

// ---------------------------------------------------------------------------
// Persistent single-wave center loss with a per-warp cp.async ring.
// Features stream GMEM->SMEM via cp.async.cg (L1-bypass), 512B chunks,
// 3-buffer ring, issue-ahead 2: every warp keeps ~1KB of DRAM reads in
// flight CONTINUOUSLY with no register or occupancy cost. Centers stay in
// the (still ~132KB) L1. Each lane consumes exactly the bytes it copied, so
// per-thread cp.async.wait_group is the only sync needed in the mainloop.
// ---------------------------------------------------------------------------
__global__ void __launch_bounds__(BLK_THREADS, 8)
center_loss_persist(const float* __restrict__ feat,
                    const float* __restrict__ centers,
                    const unsigned int* __restrict__ lw,
                    float* __restrict__ out,
                    int batch, int num_classes, int nblocks) {
    __shared__ float4 sbuf[WARPS_BLK][NBUF][32];
    __shared__ float  s_warp[WARPS_BLK];
    __shared__ unsigned int s_last;

    const int warp   = threadIdx.x >> 5;
    const int lane   = threadIdx.x & 31;
    const int gw     = blockIdx.x * WARPS_BLK + warp;
    const int nwarps = nblocks * WARPS_BLK;          // 9728

    // ---- per-warp dtype probe (2 cache lines, hot after first warp) ----
    // int64 LE labels in [0,96) => all odd 32-bit words are 0.
    // False-positive for genuine int32 labels ~ (1/96)^32 ~ 0.
    unsigned int oddw = lw[2 * lane + 1];
    unsigned int any  = __ballot_sync(0xffffffffu, oddw != 0u);
    const int is64 = (any == 0u);

    const int nr      = (batch - gw + nwarps - 1) / nwarps;   // rows this warp
    const int total_t = nr * CHUNKS;

    // per-lane smem ring base (shared-space address for cp.async)
    const uint32_t sb0 =
        (uint32_t)__cvta_generic_to_shared(&sbuf[warp][0][lane]);

    // issue chunk t (always commits a group, real or empty, so that
    // wait_group counting stays aligned at the stream tail)
    auto issue = [&](int t, int buf) {
        if (t < total_t) {
            const int    k   = t >> 3;
            const int    c   = t & 7;
            const size_t row = (size_t)(gw + k * nwarps);
            const float4* src =
                (const float4*)(feat + row * FEAT_DIM) + (c << 5) + lane;
            cp_async16(sb0 + (uint32_t)buf * (32u * 16u), src);
        }
        cp_commit();
    };

    // warm-up: 2 chunks in flight
    issue(0, 0);
    issue(1, 1);

    // first label (dependent chain exposed only once per warp)
    int r   = gw;
    int lbl = 0;
    {
        int l = 0;
        if (lane == 0) l = is64 ? (int)lw[2 * r] : (int)lw[r];
        lbl = __shfl_sync(0xffffffffu, l, 0);
    }

    float wsum = 0.0f;                // per-warp running sum (fixed order)
    int t  = 0;
    int bc = 0;                       // consume buffer = t % NBUF

    for (int k = 0; k < nr; k++) {
        // prefetch next row's label (hidden under this row's work)
        const int rn = r + nwarps;
        int lbln = 0;
        if (rn < batch) {
            int l = 0;
            if (lane == 0) l = is64 ? (int)lw[2 * rn] : (int)lw[rn];
            lbln = __shfl_sync(0xffffffffu, l, 0);
        }

        const float4* crp =
            (const float4*)(centers + (size_t)lbl * FEAT_DIM) + lane;

        float acc = 0.0f;
        #pragma unroll
        for (int c = 0; c < CHUNKS; c++) {
            cp_wait<1>();                         // chunk t landed
            float4 a = sbuf[warp][bc][lane];      // own lane's data only
            float4 b = crp[c << 5];               // center: L1-resident
            float dx = a.x - b.x, dy = a.y - b.y;
            float dz = a.z - b.z, dw = a.w - b.w;
            acc = fmaf(dx, dx, acc);
            acc = fmaf(dy, dy, acc);
            acc = fmaf(dz, dz, acc);
            acc = fmaf(dw, dw, acc);

            // refill: chunk t+2 into buffer (bc+2)%NBUF (WAR distance = 1
            // full iteration + a wait_group; never the buffer just read)
            int ib = bc + 2; if (ib >= NBUF) ib -= NBUF;
            issue(t + 2, ib);
            t++;
            if (++bc == NBUF) bc = 0;
        }

        #pragma unroll
        for (int o = 16; o > 0; o >>= 1)
            acc += __shfl_xor_sync(0xffffffffu, acc, o);

        // clip(d, 1e-12, 1e12) per row, then accumulate (fixed order)
        wsum += fminf(fmaxf(acc, 1e-12f), 1e12f);

        r = rn;
        lbl = lbln;
    }
    cp_wait<0>();                     // drain (empty tail groups)

    if (lane == 0) s_warp[warp] = wsum;
    __syncthreads();

    // ---- per-block partial (fixed order -> deterministic) ----
    if (threadIdx.x == 0) {
        float tt = 0.0f;
        #pragma unroll
        for (int i = 0; i < WARPS_BLK; i++) tt += s_warp[i];
        g_partials[blockIdx.x] = tt;
        __threadfence();
        unsigned int v = atomicAdd(&g_done, 1u);
        s_last = (v == (unsigned int)(nblocks - 1)) ? 1u : 0u;
    }
    __syncthreads();

    // ---- last block: deterministic double-precision final reduce ----
    if (s_last) {
        __threadfence();              // acquire: observe all g_partials
        double dacc = 0.0;
        for (int i = threadIdx.x; i < nblocks; i += BLK_THREADS)
            dacc += (double)g_partials[i];

        // overlay the (now dead) cp.async ring as the reduce scratch
        double* sd = (double*)&sbuf[0][0][0];     // 12KB >= 2KB needed
        sd[threadIdx.x] = dacc;
        __syncthreads();
        #pragma unroll
        for (int st = BLK_THREADS / 2; st > 0; st >>= 1) {
            if (threadIdx.x < st) sd[threadIdx.x] += sd[threadIdx.x + st];
            __syncthreads();
        }
        if (threadIdx.x == 0) {
            g_done = 0;   // reset for next graph replay (deterministic state)
            out[0] = (float)(sd[0] / (double)batch
                             + (double)(num_classes - 1) * 1e-12);
        }
    }
}

// ---------------------------------------------------------------------------
extern "C" void kernel_launch(void* const* d_in, const int* in_sizes, int n_in,
                              void* d_out, int out_size) {
    const float*        feat    = (const float*)d_in[0];
    const float*        centers = (const float*)d_in[1];
    const unsigned int* labels  = (const unsigned int*)d_in[2];

    const int batch       = in_sizes[0] / FEAT_DIM;   // 65536
    const int num_classes = in_sizes[1] / FEAT_DIM;   // 96

    center_loss_persist<<<GRID_BLKS, BLK_THREADS>>>(feat, centers, labels,
                                                    (float*)d_out,
                                                    batch, num_classes,
                                                    GRID_BLKS);
}

// round 14
// speedup vs baseline: 1.0890x; 1.0890x over previous
#include <cuda_runtime.h>
#include <cstdint>

#define FEAT_DIM    1024
#define BLK_THREADS 256
#define WARPS_BLK   8
#define GRID_BLKS   912             // 152 SMs x 6 blocks (42-reg class) -> one wave
#define MAX_BLOCKS  2048

// Static scratch (allocation-free per harness rules)
__device__ float        g_partials[MAX_BLOCKS];
__device__ unsigned int g_done;     // self-resetting last-block counter

// ---------------------------------------------------------------------------
// Persistent single-wave center loss with A/B register double-buffering:
// 4 feature LDG.128 are in flight during EVERY phase of the row loop
// (issue B=half1 before consuming A=half0; issue A=next-row-half0 -- features
// are label-independent -- before consuming B). Continuous memory duty at
// MLP4 with 48 warps/SM, no smem, no sync instructions in the mainloop.
// Centers remain L1-resident (features use .cs evict-first).
// ---------------------------------------------------------------------------
__global__ void __launch_bounds__(BLK_THREADS, 6)
center_loss_persist(const float* __restrict__ feat,
                    const float* __restrict__ centers,
                    const unsigned int* __restrict__ lw,
                    float* __restrict__ out,
                    int batch, int num_classes, int nblocks) {
    const int warp   = threadIdx.x >> 5;
    const int lane   = threadIdx.x & 31;
    const int gw     = blockIdx.x * WARPS_BLK + warp;
    const int nwarps = nblocks * WARPS_BLK;          // 7296

    // ---- per-warp dtype probe (2 cache lines, hot after first warp) ----
    // int64 LE labels in [0,96) => all odd 32-bit words are 0.
    // False-positive for genuine int32 labels ~ (1/96)^32 ~ 0.
    unsigned int oddw = lw[2 * lane + 1];
    unsigned int any  = __ballot_sync(0xffffffffu, oddw != 0u);
    const int is64 = (any == 0u);

    float wsum = 0.0f;                 // per-warp running sum (fixed order)
    int r = gw;                        // every warp has >= 8 rows (gw < 7296)

    // first label (dependent chain exposed only once per warp)
    int lbl;
    {
        int l = 0;
        if (lane == 0) l = is64 ? (int)lw[2 * r] : (int)lw[r];
        lbl = __shfl_sync(0xffffffffu, l, 0);
    }

    const float4* fr = (const float4*)(feat + (size_t)r * FEAT_DIM) + lane;

    // prologue: half0 of row 0 in flight
    float4 A[4];
    #pragma unroll
    for (int i = 0; i < 4; i++) A[i] = __ldcs(&fr[32 * i]);

    for (;;) {
        const int  rn       = r + nwarps;
        const bool has_next = (rn < batch);

        // prefetch next row's label (hidden under this row's work)
        int lbln = 0;
        if (has_next) {
            int l = 0;
            if (lane == 0) l = is64 ? (int)lw[2 * rn] : (int)lw[rn];
            lbln = __shfl_sync(0xffffffffu, l, 0);
        }

        const float4* cr =
            (const float4*)(centers + (size_t)lbl * FEAT_DIM) + lane;

        // issue half1 BEFORE consuming half0 -> loads in flight during consume
        float4 B[4];
        #pragma unroll
        for (int i = 0; i < 4; i++) B[i] = __ldcs(&fr[128 + 32 * i]);

        float acc = 0.0f;
        #pragma unroll
        for (int i = 0; i < 4; i++) {          // consume A vs L1-hot centers
            float4 b = cr[32 * i];
            float dx = A[i].x - b.x, dy = A[i].y - b.y;
            float dz = A[i].z - b.z, dw = A[i].w - b.w;
            acc = fmaf(dx, dx, acc);
            acc = fmaf(dy, dy, acc);
            acc = fmaf(dz, dz, acc);
            acc = fmaf(dw, dw, acc);
        }

        // issue NEXT row's half0 (label-independent) before consuming B
        const float4* frn = has_next
            ? (const float4*)(feat + (size_t)rn * FEAT_DIM) + lane
            : fr;                               // tail: re-read hot line (harmless)
        #pragma unroll
        for (int i = 0; i < 4; i++) A[i] = __ldcs(&frn[32 * i]);

        #pragma unroll
        for (int i = 0; i < 4; i++) {          // consume B vs L1-hot centers
            float4 b = cr[128 + 32 * i];
            float dx = B[i].x - b.x, dy = B[i].y - b.y;
            float dz = B[i].z - b.z, dw = B[i].w - b.w;
            acc = fmaf(dx, dx, acc);
            acc = fmaf(dy, dy, acc);
            acc = fmaf(dz, dz, acc);
            acc = fmaf(dw, dw, acc);
        }

        #pragma unroll
        for (int o = 16; o > 0; o >>= 1)
            acc += __shfl_xor_sync(0xffffffffu, acc, o);

        // clip(d, 1e-12, 1e12) per row, then accumulate (fixed order)
        wsum += fminf(fmaxf(acc, 1e-12f), 1e12f);

        if (!has_next) break;
        r = rn; lbl = lbln; fr = frn;
    }

    __shared__ float s[WARPS_BLK];
    if (lane == 0) s[warp] = wsum;
    __syncthreads();

    // ---- per-block partial (fixed order -> deterministic) ----
    __shared__ unsigned int s_last;
    if (threadIdx.x == 0) {
        float t = 0.0f;
        #pragma unroll
        for (int i = 0; i < WARPS_BLK; i++) t += s[i];
        g_partials[blockIdx.x] = t;
        __threadfence();
        unsigned int v = atomicAdd(&g_done, 1u);
        s_last = (v == (unsigned int)(nblocks - 1)) ? 1u : 0u;
    }
    __syncthreads();

    // ---- last block: deterministic double-precision final reduce ----
    if (s_last) {
        __threadfence();   // acquire: observe all g_partials writes
        double dacc = 0.0;
        for (int i = threadIdx.x; i < nblocks; i += BLK_THREADS)
            dacc += (double)g_partials[i];

        __shared__ double sd[BLK_THREADS];
        sd[threadIdx.x] = dacc;
        __syncthreads();
        #pragma unroll
        for (int st = BLK_THREADS / 2; st > 0; st >>= 1) {
            if (threadIdx.x < st) sd[threadIdx.x] += sd[threadIdx.x + st];
            __syncthreads();
        }
        if (threadIdx.x == 0) {
            g_done = 0;   // reset for next graph replay (deterministic state)
            out[0] = (float)(sd[0] / (double)batch
                             + (double)(num_classes - 1) * 1e-12);
        }
    }
}

// ---------------------------------------------------------------------------
extern "C" void kernel_launch(void* const* d_in, const int* in_sizes, int n_in,
                              void* d_out, int out_size) {
    const float*        feat    = (const float*)d_in[0];
    const float*        centers = (const float*)d_in[1];
    const unsigned int* labels  = (const unsigned int*)d_in[2];

    const int batch       = in_sizes[0] / FEAT_DIM;   // 65536
    const int num_classes = in_sizes[1] / FEAT_DIM;   // 96

    center_loss_persist<<<GRID_BLKS, BLK_THREADS>>>(feat, centers, labels,
                                                    (float*)d_out,
                                                    batch, num_classes,
                                                    GRID_BLKS);
}